// round 1
// baseline (speedup 1.0000x reference)
#include <cuda_runtime.h>

#define BATCH 256
#define TLEN  4096
#define NNEUR 16
#define BT    (BATCH * TLEN)

// 64 MB scratch for per-neuron stress traces: layout (N, B, T)
__device__ float g_outs[NNEUR * BT];

__device__ __forceinline__ float tanh_fast(float v) {
    // tanh(v) = 1 - 2/(exp(2v)+1); exp(inf)->inf -> 1, exp(-inf)->0 -> -1
    float e = __expf(2.0f * v);
    return 1.0f - __fdividef(2.0f, e + 1.0f);
}

// ---------------------------------------------------------------------------
// Kernel 1: the sequential scan. Grid: 1024 blocks x 64 threads.
// Block j: batch b = j>>2, neurons nbase..nbase+3 where nbase=(j&3)*4.
// Each warp handles 2 chains (2 neurons, same b): lanes 0-15 neuron n0,
// lanes 16-31 neuron n0+1.
// ---------------------------------------------------------------------------
__global__ void __launch_bounds__(64) pinn_scan_kernel(
    const float* __restrict__ x,      // (B, T, 2)
    const float* __restrict__ W1,     // (16, 32, 3)
    const float* __restrict__ b1,     // (16, 32)
    const float* __restrict__ W2,     // (16, 16, 32)
    const float* __restrict__ b2,     // (16, 16)
    const float* __restrict__ W3,     // (16, 1, 16)
    const float* __restrict__ b3,     // (16, 1)
    const float* __restrict__ logE,   // (16, 1)
    const float* __restrict__ logeta, // (16, 1)
    const float* __restrict__ imp)    // (16, 1)
{
    const int j     = blockIdx.x;
    const int b     = j >> 2;
    const int nbase = (j & 3) << 2;
    const int tid   = threadIdx.x;
    const int w     = tid >> 5;        // warp in block: 0..1
    const int lane  = tid & 31;
    const int grp   = lane >> 4;       // 0/1 -> which neuron of the pair
    const int gl    = lane & 15;       // lane within group
    const int n     = nbase + (w << 1) + grp;

    // ---- per-lane weights (registers) ----
    const int i0 = gl << 1, i1 = i0 + 1;      // the two h1 rows this lane owns
    const float* W1n = W1 + n * 96;           // (32,3) row-major
    const float w1a0 = W1n[i0 * 3 + 0], w1a1 = W1n[i0 * 3 + 1], w1a2 = W1n[i0 * 3 + 2];
    const float w1b0 = W1n[i1 * 3 + 0], w1b1 = W1n[i1 * 3 + 1], w1b2 = W1n[i1 * 3 + 2];
    const float b1a  = b1[n * 32 + i0];
    const float b1b  = b1[n * 32 + i1];

    float w2r[32];                            // W2[n][gl][0..31] (one h2 row)
    {
        const float4* p = (const float4*)(W2 + n * 512 + gl * 32);
#pragma unroll
        for (int q = 0; q < 8; q++) {
            float4 v = p[q];
            w2r[4 * q + 0] = v.x; w2r[4 * q + 1] = v.y;
            w2r[4 * q + 2] = v.z; w2r[4 * q + 3] = v.w;
        }
    }
    const float b2k  = b2[n * 16 + gl];
    const float w3k  = W3[n * 16 + gl];
    const float b3n  = b3[n];
    const float Ev   = expf(logE[n]);
    const float etav = expf(logeta[n]);
    const float iwv  = 1.0f / (1.0f + expf(-imp[n]));

    // h1 staging: [warp][parity][grp][40] (pad 40 keeps the two groups'
    // LDS.128 broadcasts on distinct bank quads)
    __shared__ float sh[2][2][2][40];

    const float2* x2 = (const float2*)x;      // x[b][t] as float2
    float* outp = g_outs + n * BT + b * TLEN;

    float prev = 0.0f;
    float keep = 0.0f;

    for (int t0 = 0; t0 < TLEN; t0 += 16) {
        // lanes 0..15 (dup on 16..31) hold x for steps t0..t0+15
        float2 xs = x2[b * TLEN + t0 + gl];

#pragma unroll
        for (int u = 0; u < 16; u++) {
            const int par = u & 1;
            float strain = __shfl_sync(0xffffffffu, xs.x, u);
            float rate   = __shfl_sync(0xffffffffu, xs.y, u);

            float m  = fmaf(Ev, strain, etav * rate);

            float za = fmaf(w1a2, prev, fmaf(w1a1, rate, fmaf(w1a0, strain, b1a)));
            float zb = fmaf(w1b2, prev, fmaf(w1b1, rate, fmaf(w1b0, strain, b1b)));
            float2 hh = make_float2(tanh_fast(za), tanh_fast(zb));

            *(float2*)&sh[w][par][grp][i0] = hh;
            __syncwarp();

            const float* hb = &sh[w][par][grp][0];
            float a0 = b2k, a1 = 0.0f, a2 = 0.0f, a3 = 0.0f;
#pragma unroll
            for (int h = 0; h < 32; h += 4) {
                float4 v = *(const float4*)(hb + h);
                a0 = fmaf(w2r[h + 0], v.x, a0);
                a1 = fmaf(w2r[h + 1], v.y, a1);
                a2 = fmaf(w2r[h + 2], v.z, a2);
                a3 = fmaf(w2r[h + 3], v.w, a3);
            }
            float h2v = tanh_fast((a0 + a1) + (a2 + a3));

            // corr = sum over the 16 lanes of the group of w3k*h2
            float pr = w3k * h2v;
            pr += __shfl_xor_sync(0xffffffffu, pr, 1);
            pr += __shfl_xor_sync(0xffffffffu, pr, 2);
            pr += __shfl_xor_sync(0xffffffffu, pr, 4);
            pr += __shfl_xor_sync(0xffffffffu, pr, 8);

            float stress = (m + (pr + b3n)) * iwv;
            prev = stress;
            if (gl == u) keep = stress;   // lane u of each group keeps step t0+u
        }
        // coalesced 64B dump per group (lanes write t0+gl)
        outp[t0 + gl] = keep;
    }
}

// ---------------------------------------------------------------------------
// Kernel 2: mixing head. One thread per (b,t); computes all 4 p outputs.
// out[p,b,t] = Wf2 . relu(Wf1 @ (outs[l*4+p,b,t]*S[l]*w[l]) + bf1) + bf2
// ---------------------------------------------------------------------------
__global__ void __launch_bounds__(256) pinn_combine_kernel(
    const float* __restrict__ imp,    // (16,1)
    const float* __restrict__ lw,     // (4,)
    const float* __restrict__ Wf1,    // (16,4)
    const float* __restrict__ bf1,    // (16,)
    const float* __restrict__ Wf2,    // (1,16)
    const float* __restrict__ bf2,    // (1,)
    float* __restrict__ out)          // (4, B, T)
{
    __shared__ float a_sh[16][4];
    __shared__ float wf2_sh[16];
    __shared__ float bf1_sh[16];
    __shared__ float bf2_sh;

    if (threadIdx.x < 16) {
        const int f = threadIdx.x;
        // softmax over layer_weights
        float m  = fmaxf(fmaxf(lw[0], lw[1]), fmaxf(lw[2], lw[3]));
        float e0 = expf(lw[0] - m), e1 = expf(lw[1] - m);
        float e2 = expf(lw[2] - m), e3 = expf(lw[3] - m);
        float es = e0 + e1 + e2 + e3;
        float wl[4] = { e0 / es, e1 / es, e2 / es, e3 / es };
#pragma unroll
        for (int l = 0; l < 4; l++) {
            float s = 0.0f;
#pragma unroll
            for (int p = 0; p < 4; p++)
                s += 1.0f / (1.0f + expf(-imp[l * 4 + p]));
            float S  = s / (s + 1e-8f);
            a_sh[f][l] = Wf1[f * 4 + l] * (S * wl[l]);
        }
        wf2_sh[f] = Wf2[f];
        bf1_sh[f] = bf1[f];
        if (f == 0) bf2_sh = bf2[0];
    }
    __syncthreads();

    const int idx = blockIdx.x * 256 + threadIdx.x;   // idx = b*T + t, < BT exactly
    if (idx >= BT) return;

    float y[4][4];  // [l][p]
#pragma unroll
    for (int l = 0; l < 4; l++)
#pragma unroll
        for (int p = 0; p < 4; p++)
            y[l][p] = g_outs[(l * 4 + p) * BT + idx];

#pragma unroll
    for (int p = 0; p < 4; p++) {
        float o = bf2_sh;
#pragma unroll
        for (int f = 0; f < 16; f++) {
            float h = bf1_sh[f];
#pragma unroll
            for (int l = 0; l < 4; l++)
                h = fmaf(a_sh[f][l], y[l][p], h);
            o = fmaf(wf2_sh[f], fmaxf(h, 0.0f), o);
        }
        out[p * BT + idx] = o;
    }
}

// ---------------------------------------------------------------------------
extern "C" void kernel_launch(void* const* d_in, const int* in_sizes, int n_in,
                              void* d_out, int out_size) {
    const float* x    = (const float*)d_in[0];
    const float* W1   = (const float*)d_in[1];
    const float* b1   = (const float*)d_in[2];
    const float* W2   = (const float*)d_in[3];
    const float* b2   = (const float*)d_in[4];
    const float* W3   = (const float*)d_in[5];
    const float* b3   = (const float*)d_in[6];
    const float* logE = (const float*)d_in[7];
    const float* loge = (const float*)d_in[8];
    const float* imp  = (const float*)d_in[9];
    const float* lw   = (const float*)d_in[10];
    const float* Wf1  = (const float*)d_in[11];
    const float* bf1  = (const float*)d_in[12];
    const float* Wf2  = (const float*)d_in[13];
    const float* bf2  = (const float*)d_in[14];
    float* out = (float*)d_out;

    pinn_scan_kernel<<<1024, 64>>>(x, W1, b1, W2, b2, W3, b3, logE, loge, imp);
    pinn_combine_kernel<<<BT / 256, 256>>>(imp, lw, Wf1, bf1, Wf2, bf2, out);
}

// round 2
// speedup vs baseline: 1.1935x; 1.1935x over previous
#include <cuda_runtime.h>

#define BATCH 256
#define TLEN  4096
#define NNEUR 16
#define BT    (BATCH * TLEN)

// 64 MB scratch for per-neuron stress traces: layout (N, B, T)
__device__ float g_outs[NNEUR * BT];

__device__ __forceinline__ float tanh_mufu(float v) {
    float r;
    asm("tanh.approx.f32 %0, %1;" : "=f"(r) : "f"(v));
    return r;
}

// ---------------------------------------------------------------------------
// Kernel 1: the sequential scan. Grid: 1024 blocks x 64 threads.
// Block j: batch b = j>>2, neurons nbase..nbase+3 where nbase=(j&3)*4.
// Each warp handles 2 chains (2 neurons, same b): lanes 0-15 neuron n0,
// lanes 16-31 neuron n0+1.
// ---------------------------------------------------------------------------
__global__ void __launch_bounds__(64) pinn_scan_kernel(
    const float* __restrict__ x,      // (B, T, 2)
    const float* __restrict__ W1,     // (16, 32, 3)
    const float* __restrict__ b1,     // (16, 32)
    const float* __restrict__ W2,     // (16, 16, 32)
    const float* __restrict__ b2,     // (16, 16)
    const float* __restrict__ W3,     // (16, 1, 16)
    const float* __restrict__ b3,     // (16, 1)
    const float* __restrict__ logE,   // (16, 1)
    const float* __restrict__ logeta, // (16, 1)
    const float* __restrict__ imp)    // (16, 1)
{
    const int j     = blockIdx.x;
    const int b     = j >> 2;
    const int nbase = (j & 3) << 2;
    const int tid   = threadIdx.x;
    const int w     = tid >> 5;        // warp in block: 0..1
    const int lane  = tid & 31;
    const int grp   = lane >> 4;       // 0/1 -> which neuron of the pair
    const int gl    = lane & 15;       // lane within group
    const int n     = nbase + (w << 1) + grp;

    // ---- per-lane weights (registers) ----
    const int i0 = gl << 1, i1 = i0 + 1;      // the two h1 rows this lane owns
    const float* W1n = W1 + n * 96;           // (32,3) row-major
    const float w1a0 = W1n[i0 * 3 + 0], w1a1 = W1n[i0 * 3 + 1], w1a2 = W1n[i0 * 3 + 2];
    const float w1b0 = W1n[i1 * 3 + 0], w1b1 = W1n[i1 * 3 + 1], w1b2 = W1n[i1 * 3 + 2];
    const float b1a  = b1[n * 32 + i0];
    const float b1b  = b1[n * 32 + i1];

    float w2r[32];                            // W2[n][gl][0..31] (one h2 row)
    {
        const float4* p = (const float4*)(W2 + n * 512 + gl * 32);
#pragma unroll
        for (int q = 0; q < 8; q++) {
            float4 v = p[q];
            w2r[4 * q + 0] = v.x; w2r[4 * q + 1] = v.y;
            w2r[4 * q + 2] = v.z; w2r[4 * q + 3] = v.w;
        }
    }
    const float b2k  = b2[n * 16 + gl];
    const float w3k  = W3[n * 16 + gl];
    const float b3n  = b3[n];
    const float Ev   = expf(logE[n]);
    const float etav = expf(logeta[n]);
    const float iwv  = 1.0f / (1.0f + expf(-imp[n]));

    // Per-warp SMEM staging. Group strides chosen so the two groups'
    // broadcast LDS.128 reads never share bank quads:
    //   h1: stride 36 floats (offset 4 banks), pr: stride 20 floats.
    __shared__ float  sh_h1[2][80];    // [warp][grp*36 + 0..31], 16B-aligned bases
    __shared__ float  sh_pr[2][48];    // [warp][grp*20 + 0..15]
    __shared__ float2 sh_x [2][16];    // [warp][u]

    const float2* x2 = (const float2*)x;      // x[b][t] as float2
    float* outp = g_outs + n * BT + b * TLEN;

    float prev = 0.0f;
    float keep = 0.0f;

    for (int t0 = 0; t0 < TLEN; t0 += 16) {
        // stage this 16-step window of x into SMEM (one copy per warp)
        if (grp == 0) sh_x[w][gl] = x2[b * TLEN + t0 + gl];
        __syncwarp();

#pragma unroll
        for (int u = 0; u < 16; u++) {
            float2 xt = sh_x[w][u];           // broadcast LDS.64 (off-path)
            const float strain = xt.x, rate = xt.y;

            float m   = fmaf(Ev, strain, etav * rate);
            float zba = fmaf(w1a1, rate, fmaf(w1a0, strain, b1a));
            float zbb = fmaf(w1b1, rate, fmaf(w1b0, strain, b1b));

            // ---- critical path begins: prev -> ... -> stress ----
            float ha = tanh_mufu(fmaf(w1a2, prev, zba));
            float hb = tanh_mufu(fmaf(w1b2, prev, zbb));

            *(float2*)&sh_h1[w][grp * 36 + i0] = make_float2(ha, hb);
            __syncwarp();

            const float* hbase = &sh_h1[w][grp * 36];
            float a0 = b2k, a1 = 0.0f, a2 = 0.0f, a3 = 0.0f;
#pragma unroll
            for (int hj = 0; hj < 32; hj += 4) {
                float4 v = *(const float4*)(hbase + hj);
                a0 = fmaf(w2r[hj + 0], v.x, a0);
                a1 = fmaf(w2r[hj + 1], v.y, a1);
                a2 = fmaf(w2r[hj + 2], v.z, a2);
                a3 = fmaf(w2r[hj + 3], v.w, a3);
            }
            float h2v = tanh_mufu((a0 + a1) + (a2 + a3));

            sh_pr[w][grp * 20 + gl] = w3k * h2v;
            __syncwarp();

            const float4* pb = (const float4*)&sh_pr[w][grp * 20];
            float4 p0 = pb[0], p1 = pb[1], p2 = pb[2], p3 = pb[3];
            float s01 = ((p0.x + p0.y) + (p0.z + p0.w)) + ((p1.x + p1.y) + (p1.z + p1.w));
            float s23 = ((p2.x + p2.y) + (p2.z + p2.w)) + ((p3.x + p3.y) + (p3.z + p3.w));

            float stress = (m + ((s01 + s23) + b3n)) * iwv;
            prev = stress;
            if (gl == u) keep = stress;       // lane u of each group keeps step t0+u
        }
        // coalesced 64B dump per group
        outp[t0 + gl] = keep;
    }
}

// ---------------------------------------------------------------------------
// Kernel 2: mixing head, float4-vectorized. One thread per 4 (b,t) slots.
// out[p,b,t] = Wf2 . relu(Wf1 @ (outs[l*4+p,b,t]*S[l]*w[l]) + bf1) + bf2
// ---------------------------------------------------------------------------
__global__ void __launch_bounds__(256) pinn_combine_kernel(
    const float* __restrict__ imp,    // (16,1)
    const float* __restrict__ lw,     // (4,)
    const float* __restrict__ Wf1,    // (16,4)
    const float* __restrict__ bf1,    // (16,)
    const float* __restrict__ Wf2,    // (1,16)
    const float* __restrict__ bf2,    // (1,)
    float* __restrict__ out)          // (4, B, T)
{
    __shared__ float a_sh[16][4];
    __shared__ float wf2_sh[16];
    __shared__ float bf1_sh[16];
    __shared__ float bf2_sh;

    if (threadIdx.x < 16) {
        const int f = threadIdx.x;
        float mx = fmaxf(fmaxf(lw[0], lw[1]), fmaxf(lw[2], lw[3]));
        float e0 = expf(lw[0] - mx), e1 = expf(lw[1] - mx);
        float e2 = expf(lw[2] - mx), e3 = expf(lw[3] - mx);
        float es = e0 + e1 + e2 + e3;
        float wl[4] = { e0 / es, e1 / es, e2 / es, e3 / es };
#pragma unroll
        for (int l = 0; l < 4; l++) {
            float s = 0.0f;
#pragma unroll
            for (int p = 0; p < 4; p++)
                s += 1.0f / (1.0f + expf(-imp[l * 4 + p]));
            float S  = s / (s + 1e-8f);
            a_sh[f][l] = Wf1[f * 4 + l] * (S * wl[l]);
        }
        wf2_sh[f] = Wf2[f];
        bf1_sh[f] = bf1[f];
        if (f == 0) bf2_sh = bf2[0];
    }
    __syncthreads();

    const int idx4 = (blockIdx.x * 256 + threadIdx.x) * 4;  // < BT exactly

    float4 y[16];
#pragma unroll
    for (int nn = 0; nn < 16; nn++)
        y[nn] = *(const float4*)&g_outs[nn * BT + idx4];

#pragma unroll
    for (int p = 0; p < 4; p++) {
        float4 o = make_float4(bf2_sh, bf2_sh, bf2_sh, bf2_sh);
#pragma unroll
        for (int f = 0; f < 16; f++) {
            float4 h = make_float4(bf1_sh[f], bf1_sh[f], bf1_sh[f], bf1_sh[f]);
#pragma unroll
            for (int l = 0; l < 4; l++) {
                float a = a_sh[f][l];
                float4 v = y[l * 4 + p];
                h.x = fmaf(a, v.x, h.x); h.y = fmaf(a, v.y, h.y);
                h.z = fmaf(a, v.z, h.z); h.w = fmaf(a, v.w, h.w);
            }
            float wf = wf2_sh[f];
            o.x = fmaf(wf, fmaxf(h.x, 0.0f), o.x);
            o.y = fmaf(wf, fmaxf(h.y, 0.0f), o.y);
            o.z = fmaf(wf, fmaxf(h.z, 0.0f), o.z);
            o.w = fmaf(wf, fmaxf(h.w, 0.0f), o.w);
        }
        *(float4*)&out[p * BT + idx4] = o;
    }
}

// ---------------------------------------------------------------------------
extern "C" void kernel_launch(void* const* d_in, const int* in_sizes, int n_in,
                              void* d_out, int out_size) {
    const float* x    = (const float*)d_in[0];
    const float* W1   = (const float*)d_in[1];
    const float* b1   = (const float*)d_in[2];
    const float* W2   = (const float*)d_in[3];
    const float* b2   = (const float*)d_in[4];
    const float* W3   = (const float*)d_in[5];
    const float* b3   = (const float*)d_in[6];
    const float* logE = (const float*)d_in[7];
    const float* loge = (const float*)d_in[8];
    const float* imp  = (const float*)d_in[9];
    const float* lw   = (const float*)d_in[10];
    const float* Wf1  = (const float*)d_in[11];
    const float* bf1  = (const float*)d_in[12];
    const float* Wf2  = (const float*)d_in[13];
    const float* bf2  = (const float*)d_in[14];
    float* out = (float*)d_out;

    pinn_scan_kernel<<<1024, 64>>>(x, W1, b1, W2, b2, W3, b3, logE, loge, imp);
    pinn_combine_kernel<<<BT / 1024, 256>>>(imp, lw, Wf1, bf1, Wf2, bf2, out);
}

// round 4
// speedup vs baseline: 1.1995x; 1.0050x over previous
#include <cuda_runtime.h>

#define BATCH 256
#define TLEN  4096
#define NNEUR 16
#define BT    (BATCH * TLEN)

// 64 MB scratch for per-neuron stress traces: layout (N, B, T)
__device__ float g_outs[NNEUR * BT];

typedef unsigned long long u64;

__device__ __forceinline__ float tanh_mufu(float v) {
    float r;
    asm("tanh.approx.f32 %0, %1;" : "=f"(r) : "f"(v));
    return r;
}
__device__ __forceinline__ u64 pack2(float lo, float hi) {
    u64 r; asm("mov.b64 %0, {%1, %2};" : "=l"(r) : "f"(lo), "f"(hi)); return r;
}
__device__ __forceinline__ void unpack2(u64 v, float& lo, float& hi) {
    asm("mov.b64 {%0, %1}, %2;" : "=f"(lo), "=f"(hi) : "l"(v));
}
__device__ __forceinline__ u64 fma2(u64 a, u64 b, u64 c) {
    u64 d; asm("fma.rn.f32x2 %0, %1, %2, %3;" : "=l"(d) : "l"(a), "l"(b), "l"(c)); return d;
}
__device__ __forceinline__ u64 add2(u64 a, u64 b) {
    u64 d; asm("add.rn.f32x2 %0, %1, %2;" : "=l"(d) : "l"(a), "l"(b)); return d;
}

// ---------------------------------------------------------------------------
// Kernel 1: the sequential scan. Grid: 1024 blocks x 64 threads.
// Block j: batch b = j>>2, neurons nbase..nbase+3 where nbase=(j&3)*4.
// Each warp handles 2 chains (2 neurons, same b): lanes 0-15 neuron n0,
// lanes 16-31 neuron n0+1.
// Recurrence carried as sumpr (= sum_k w3_k h2_k); prev enters the next
// step only through z = A*sumpr + zoff, A = w1_2*iw (zoff off-path).
// ---------------------------------------------------------------------------
__global__ void __launch_bounds__(64) pinn_scan_kernel(
    const float* __restrict__ x,      // (B, T, 2)
    const float* __restrict__ W1,     // (16, 32, 3)
    const float* __restrict__ b1,     // (16, 32)
    const float* __restrict__ W2,     // (16, 16, 32)
    const float* __restrict__ b2,     // (16, 16)
    const float* __restrict__ W3,     // (16, 1, 16)
    const float* __restrict__ b3,     // (16, 1)
    const float* __restrict__ logE,   // (16, 1)
    const float* __restrict__ logeta, // (16, 1)
    const float* __restrict__ imp)    // (16, 1)
{
    const int j     = blockIdx.x;
    const int b     = j >> 2;
    const int nbase = (j & 3) << 2;
    const int tid   = threadIdx.x;
    const int w     = tid >> 5;        // warp in block: 0..1
    const int lane  = tid & 31;
    const int grp   = lane >> 4;       // 0/1 -> which neuron of the pair
    const int gl    = lane & 15;       // lane within group
    const int n     = nbase + (w << 1) + grp;

    // ---- per-lane weights (registers) ----
    const int i0 = gl << 1, i1 = i0 + 1;      // the two h1 rows this lane owns
    const float* W1n = W1 + n * 96;           // (32,3) row-major
    const float w1a0 = W1n[i0 * 3 + 0], w1a1 = W1n[i0 * 3 + 1], w1a2 = W1n[i0 * 3 + 2];
    const float w1b0 = W1n[i1 * 3 + 0], w1b1 = W1n[i1 * 3 + 1], w1b2 = W1n[i1 * 3 + 2];
    const float b1a  = b1[n * 32 + i0];
    const float b1b  = b1[n * 32 + i1];

    u64 w2p[16];                              // W2[n][gl][0..31] as 16 f32x2 pairs
    {
        const float4* p = (const float4*)(W2 + n * 512 + gl * 32);
#pragma unroll
        for (int q = 0; q < 8; q++) {
            float4 v = p[q];
            w2p[2 * q + 0] = pack2(v.x, v.y);
            w2p[2 * q + 1] = pack2(v.z, v.w);
        }
    }
    const float b2k  = b2[n * 16 + gl];
    const float w3k  = W3[n * 16 + gl];
    const float b3n  = b3[n];
    const float Ev   = expf(logE[n]);
    const float etav = expf(logeta[n]);
    const float iwv  = 1.0f / (1.0f + expf(-imp[n]));
    const float Aa   = w1a2 * iwv;            // prev-coupling, folded
    const float Ab   = w1b2 * iwv;
    const u64  A2    = pack2(Aa, Ab);

    // SMEM staging. Group strides keep the two groups' broadcast LDS.128
    // reads on distinct bank quads: h1 stride 36 floats, pr stride 20.
    __shared__ __align__(16) float sh_h1[2][80];
    __shared__ __align__(16) float sh_pr[2][48];
    __shared__ float2 sh_x[2][16];

    const float2* x2 = (const float2*)x;      // x[b][t] as float2
    float* outp = g_outs + n * BT + b * TLEN;

    float sumpr = 0.0f;   // carried recurrence state
    float cprev = 0.0f;   // m_{u-1} + b3n (zero-init matches prev=0)
    float keep  = 0.0f;

    for (int t0 = 0; t0 < TLEN; t0 += 16) {
        if (grp == 0) sh_x[w][gl] = x2[b * TLEN + t0 + gl];
        // sync1 of u=0 below fences this staging store

#pragma unroll
        for (int u = 0; u < 16; u++) {
            float2 xt;
            if (u == 0) { /* staged value read after sync below */ }
            // off-path work for this step (reads need no fence except u==0,
            // where sync1 below serves; safe because the read is after sync1)
            // -- we read sh_x after sync1 to also cover the staging store --

            // ---- critical path: sumpr -> z -> tanh ----
            u64 z2 = fma2(A2, pack2(sumpr, sumpr), 0);
            // NOTE: zoff added below after computing it (kept off-path by ptxas
            // reordering; we add explicitly):
            // (computed before use; see below)

            // read x (off-path)
            xt = sh_x[w][u];
            const float strain = xt.x, rate = xt.y;

            float m   = fmaf(Ev, strain, etav * rate);
            float c   = m + b3n;
            float zba = fmaf(w1a1, rate, fmaf(w1a0, strain, b1a));
            float zbb = fmaf(w1b1, rate, fmaf(w1b0, strain, b1b));
            float zoa = fmaf(Aa, cprev, zba);
            float zob = fmaf(Ab, cprev, zbb);

            float zlo, zhi;
            unpack2(z2, zlo, zhi);
            float ha = tanh_mufu(zlo + zoa);
            float hb = tanh_mufu(zhi + zob);

            *(float2*)&sh_h1[w][grp * 36 + i0] = make_float2(ha, hb);
            __syncwarp();   // sync1: fences h1 stores (and sh_x staging at u=0,
                            // and sh_pr overwrite from previous step)

            const u64* hp = (const u64*)&sh_h1[w][grp * 36];
            u64 a0 = pack2(b2k, 0.0f), a1 = 0, a2 = 0, a3 = 0;
#pragma unroll
            for (int q = 0; q < 4; q++) {
                a0 = fma2(w2p[4 * q + 0], hp[4 * q + 0], a0);
                a1 = fma2(w2p[4 * q + 1], hp[4 * q + 1], a1);
                a2 = fma2(w2p[4 * q + 2], hp[4 * q + 2], a2);
                a3 = fma2(w2p[4 * q + 3], hp[4 * q + 3], a3);
            }
            u64 t01 = add2(a0, a1), t23 = add2(a2, a3);
            float lo, hi;
            unpack2(add2(t01, t23), lo, hi);
            float h2v = tanh_mufu(lo + hi);

            sh_pr[w][grp * 20 + gl] = w3k * h2v;
            __syncwarp();   // sync2: fences pr stores (and sh_h1 overwrite next step)

            const u64* pb = (const u64*)&sh_pr[w][grp * 20];
            u64 s01 = add2(add2(pb[0], pb[1]), add2(pb[2], pb[3]));
            u64 s23 = add2(add2(pb[4], pb[5]), add2(pb[6], pb[7]));
            float rlo, rhi;
            unpack2(add2(s01, s23), rlo, rhi);
            sumpr = rlo + rhi;

            // output (off the recurrence chain)
            float stress = fmaf(iwv, sumpr, c * iwv);
            if (gl == u) keep = stress;
            cprev = c;
        }
        outp[t0 + gl] = keep;                  // coalesced 64B dump per group
    }
}

// ---------------------------------------------------------------------------
// Kernel 2: mixing head, float4-vectorized, streamed per-p (low regs).
// out[p,b,t] = Wf2 . relu(Wf1 @ (outs[l*4+p,b,t]*S[l]*w[l]) + bf1) + bf2
// ---------------------------------------------------------------------------
__global__ void __launch_bounds__(256) pinn_combine_kernel(
    const float* __restrict__ imp,    // (16,1)
    const float* __restrict__ lw,     // (4,)
    const float* __restrict__ Wf1,    // (16,4)
    const float* __restrict__ bf1,    // (16,)
    const float* __restrict__ Wf2,    // (1,16)
    const float* __restrict__ bf2,    // (1,)
    float* __restrict__ out)          // (4, B, T)
{
    __shared__ float a_sh[16][4];
    __shared__ float wf2_sh[16];
    __shared__ float bf1_sh[16];
    __shared__ float bf2_sh;

    if (threadIdx.x < 16) {
        const int f = threadIdx.x;
        float mx = fmaxf(fmaxf(lw[0], lw[1]), fmaxf(lw[2], lw[3]));
        float e0 = expf(lw[0] - mx), e1 = expf(lw[1] - mx);
        float e2 = expf(lw[2] - mx), e3 = expf(lw[3] - mx);
        float es = e0 + e1 + e2 + e3;
        float wl[4] = { e0 / es, e1 / es, e2 / es, e3 / es };
#pragma unroll
        for (int l = 0; l < 4; l++) {
            float s = 0.0f;
#pragma unroll
            for (int p = 0; p < 4; p++)
                s += 1.0f / (1.0f + expf(-imp[l * 4 + p]));
            float S  = s / (s + 1e-8f);
            a_sh[f][l] = Wf1[f * 4 + l] * (S * wl[l]);
        }
        wf2_sh[f] = Wf2[f];
        bf1_sh[f] = bf1[f];
        if (f == 0) bf2_sh = bf2[0];
    }
    __syncthreads();

    const int idx4 = (blockIdx.x * 256 + threadIdx.x) * 4;  // < BT exactly

#pragma unroll
    for (int p = 0; p < 4; p++) {
        float4 y[4];
#pragma unroll
        for (int l = 0; l < 4; l++)
            y[l] = *(const float4*)&g_outs[(l * 4 + p) * BT + idx4];

        float4 o = make_float4(bf2_sh, bf2_sh, bf2_sh, bf2_sh);
#pragma unroll
        for (int f = 0; f < 16; f++) {
            float4 h = make_float4(bf1_sh[f], bf1_sh[f], bf1_sh[f], bf1_sh[f]);
#pragma unroll
            for (int l = 0; l < 4; l++) {
                float a = a_sh[f][l];
                h.x = fmaf(a, y[l].x, h.x); h.y = fmaf(a, y[l].y, h.y);
                h.z = fmaf(a, y[l].z, h.z); h.w = fmaf(a, y[l].w, h.w);
            }
            float wf = wf2_sh[f];
            o.x = fmaf(wf, fmaxf(h.x, 0.0f), o.x);
            o.y = fmaf(wf, fmaxf(h.y, 0.0f), o.y);
            o.z = fmaf(wf, fmaxf(h.z, 0.0f), o.z);
            o.w = fmaf(wf, fmaxf(h.w, 0.0f), o.w);
        }
        *(float4*)&out[p * BT + idx4] = o;
    }
}

// ---------------------------------------------------------------------------
extern "C" void kernel_launch(void* const* d_in, const int* in_sizes, int n_in,
                              void* d_out, int out_size) {
    const float* x    = (const float*)d_in[0];
    const float* W1   = (const float*)d_in[1];
    const float* b1   = (const float*)d_in[2];
    const float* W2   = (const float*)d_in[3];
    const float* b2   = (const float*)d_in[4];
    const float* W3   = (const float*)d_in[5];
    const float* b3   = (const float*)d_in[6];
    const float* logE = (const float*)d_in[7];
    const float* loge = (const float*)d_in[8];
    const float* imp  = (const float*)d_in[9];
    const float* lw   = (const float*)d_in[10];
    const float* Wf1  = (const float*)d_in[11];
    const float* bf1  = (const float*)d_in[12];
    const float* Wf2  = (const float*)d_in[13];
    const float* bf2  = (const float*)d_in[14];
    float* out = (float*)d_out;

    pinn_scan_kernel<<<1024, 64>>>(x, W1, b1, W2, b2, W3, b3, logE, loge, imp);
    pinn_combine_kernel<<<BT / 1024, 256>>>(imp, lw, Wf1, bf1, Wf2, bf2, out);
}

// round 5
// speedup vs baseline: 1.2016x; 1.0017x over previous
#include <cuda_runtime.h>

#define BATCH 256
#define TLEN  4096
#define NNEUR 16
#define BT    (BATCH * TLEN)

// 64 MB scratch for per-neuron stress traces: layout (N, B, T)
__device__ float g_outs[NNEUR * BT];

typedef unsigned long long u64;

__device__ __forceinline__ float tanh_mufu(float v) {
    float r;
    asm("tanh.approx.f32 %0, %1;" : "=f"(r) : "f"(v));
    return r;
}
__device__ __forceinline__ u64 pack2(float lo, float hi) {
    u64 r; asm("mov.b64 %0, {%1, %2};" : "=l"(r) : "f"(lo), "f"(hi)); return r;
}
__device__ __forceinline__ void unpack2(u64 v, float& lo, float& hi) {
    asm("mov.b64 {%0, %1}, %2;" : "=f"(lo), "=f"(hi) : "l"(v));
}
__device__ __forceinline__ u64 fma2(u64 a, u64 b, u64 c) {
    u64 d; asm("fma.rn.f32x2 %0, %1, %2, %3;" : "=l"(d) : "l"(a), "l"(b), "l"(c)); return d;
}
__device__ __forceinline__ u64 add2(u64 a, u64 b) {
    u64 d; asm("add.rn.f32x2 %0, %1, %2;" : "=l"(d) : "l"(a), "l"(b)); return d;
}

// ---------------------------------------------------------------------------
// Kernel 1: the sequential scan. Grid: 1024 blocks x 64 threads.
// Block j: batch b = j>>2, neurons nbase..nbase+3 where nbase=(j&3)*4.
// Each warp handles 2 chains (2 neurons, same b): lanes 0-15 neuron n0,
// lanes 16-31 neuron n0+1.
// Recurrence carried as sumpr (= sum_k w3_k h2_k); prev enters the next
// step only through z = A*sumpr + zoff, A = w1_2*iw (zoff off-path).
// Per-lane-step smem ops kept to 15 (LDS.128 everywhere possible): the
// MIO/LDS pipe, not FMA, was the binding resource in earlier rounds.
// ---------------------------------------------------------------------------
__global__ void __launch_bounds__(64) pinn_scan_kernel(
    const float* __restrict__ x,      // (B, T, 2)
    const float* __restrict__ W1,     // (16, 32, 3)
    const float* __restrict__ b1,     // (16, 32)
    const float* __restrict__ W2,     // (16, 16, 32)
    const float* __restrict__ b2,     // (16, 16)
    const float* __restrict__ W3,     // (16, 1, 16)
    const float* __restrict__ b3,     // (16, 1)
    const float* __restrict__ logE,   // (16, 1)
    const float* __restrict__ logeta, // (16, 1)
    const float* __restrict__ imp)    // (16, 1)
{
    const int j     = blockIdx.x;
    const int b     = j >> 2;
    const int nbase = (j & 3) << 2;
    const int tid   = threadIdx.x;
    const int w     = tid >> 5;        // warp in block: 0..1
    const int lane  = tid & 31;
    const int grp   = lane >> 4;       // 0/1 -> which neuron of the pair
    const int gl    = lane & 15;       // lane within group
    const int n     = nbase + (w << 1) + grp;

    // ---- per-lane weights (registers) ----
    const int i0 = gl << 1, i1 = i0 + 1;      // the two h1 rows this lane owns
    const float* W1n = W1 + n * 96;           // (32,3) row-major
    const float w1a0 = W1n[i0 * 3 + 0], w1a1 = W1n[i0 * 3 + 1], w1a2 = W1n[i0 * 3 + 2];
    const float w1b0 = W1n[i1 * 3 + 0], w1b1 = W1n[i1 * 3 + 1], w1b2 = W1n[i1 * 3 + 2];
    const float b1a  = b1[n * 32 + i0];
    const float b1b  = b1[n * 32 + i1];

    u64 w2p[16];                              // W2[n][gl][0..31] as 16 f32x2 pairs
    {
        const float4* p = (const float4*)(W2 + n * 512 + gl * 32);
#pragma unroll
        for (int q = 0; q < 8; q++) {
            float4 v = p[q];
            w2p[2 * q + 0] = pack2(v.x, v.y);
            w2p[2 * q + 1] = pack2(v.z, v.w);
        }
    }
    const float b2k  = b2[n * 16 + gl];
    const u64  b2k2  = pack2(b2k, 0.0f);      // hoisted accumulator init
    const float w3k  = W3[n * 16 + gl];
    const float b3n  = b3[n];
    const float Ev   = expf(logE[n]);
    const float etav = expf(logeta[n]);
    const float iwv  = 1.0f / (1.0f + expf(-imp[n]));
    const float Aa   = w1a2 * iwv;            // prev-coupling, folded
    const float Ab   = w1b2 * iwv;

    // SMEM staging. Group strides keep the two groups' broadcast LDS.128
    // reads on distinct bank quads: h1 stride 36 floats, pr stride 20.
    __shared__ __align__(16) float sh_h1[2][80];
    __shared__ __align__(16) float sh_pr[2][48];
    __shared__ float2 sh_x[2][16];

    const float2* x2 = (const float2*)x;      // x[b][t] as float2
    float* outp = g_outs + n * BT + b * TLEN;

    float sumpr = 0.0f;   // carried recurrence state
    float cprev = 0.0f;   // m_{u-1} + b3n (zero-init matches prev=0)
    float keep  = 0.0f;

    for (int t0 = 0; t0 < TLEN; t0 += 16) {
        if (grp == 0) sh_x[w][gl] = x2[b * TLEN + t0 + gl];
        __syncwarp();

#pragma unroll
        for (int u = 0; u < 16; u++) {
            float2 xt = sh_x[w][u];           // broadcast LDS.64 (off-path)
            const float strain = xt.x, rate = xt.y;

            // off-path work for this step
            float m   = fmaf(Ev, strain, etav * rate);
            float c   = m + b3n;
            float zba = fmaf(w1a1, rate, fmaf(w1a0, strain, b1a));
            float zbb = fmaf(w1b1, rate, fmaf(w1b0, strain, b1b));
            float zoa = fmaf(Aa, cprev, zba);
            float zob = fmaf(Ab, cprev, zbb);

            // ---- critical path: sumpr -> z -> tanh -> h2 -> reduce ----
            float ha = tanh_mufu(fmaf(Aa, sumpr, zoa));
            float hb = tanh_mufu(fmaf(Ab, sumpr, zob));

            *(float2*)&sh_h1[w][grp * 36 + i0] = make_float2(ha, hb);
            __syncwarp();   // sync1: fences h1 stores + sh_pr overwrite

            const float4* hp4 = (const float4*)&sh_h1[w][grp * 36];
            u64 a0 = b2k2, a1 = 0, a2 = 0, a3 = 0;
#pragma unroll
            for (int q = 0; q < 4; q++) {
                float4 v0 = hp4[2 * q + 0];   // LDS.128
                float4 v1 = hp4[2 * q + 1];   // LDS.128
                a0 = fma2(w2p[4 * q + 0], pack2(v0.x, v0.y), a0);
                a1 = fma2(w2p[4 * q + 1], pack2(v0.z, v0.w), a1);
                a2 = fma2(w2p[4 * q + 2], pack2(v1.x, v1.y), a2);
                a3 = fma2(w2p[4 * q + 3], pack2(v1.z, v1.w), a3);
            }
            u64 t01 = add2(a0, a1), t23 = add2(a2, a3);
            float lo, hi;
            unpack2(add2(t01, t23), lo, hi);
            float h2v = tanh_mufu(lo + hi);

            sh_pr[w][grp * 20 + gl] = w3k * h2v;
            __syncwarp();   // sync2: fences pr stores + sh_h1 overwrite

            const float4* pb4 = (const float4*)&sh_pr[w][grp * 20];
            float4 p0 = pb4[0], p1 = pb4[1], p2 = pb4[2], p3 = pb4[3];  // 4x LDS.128
            u64 s01 = add2(pack2(p0.x, p0.y), pack2(p0.z, p0.w));
            u64 s23 = add2(pack2(p1.x, p1.y), pack2(p1.z, p1.w));
            u64 s45 = add2(pack2(p2.x, p2.y), pack2(p2.z, p2.w));
            u64 s67 = add2(pack2(p3.x, p3.y), pack2(p3.z, p3.w));
            float rlo, rhi;
            unpack2(add2(add2(s01, s23), add2(s45, s67)), rlo, rhi);
            sumpr = rlo + rhi;

            // output (off the recurrence chain)
            float stress = fmaf(iwv, sumpr, c * iwv);
            if (gl == u) keep = stress;
            cprev = c;
        }
        outp[t0 + gl] = keep;                  // coalesced 64B dump per group
    }
}

// ---------------------------------------------------------------------------
// Kernel 2: mixing head, float4-vectorized, streamed per-p (low regs).
// out[p,b,t] = Wf2 . relu(Wf1 @ (outs[l*4+p,b,t]*S[l]*w[l]) + bf1) + bf2
// ---------------------------------------------------------------------------
__global__ void __launch_bounds__(256) pinn_combine_kernel(
    const float* __restrict__ imp,    // (16,1)
    const float* __restrict__ lw,     // (4,)
    const float* __restrict__ Wf1,    // (16,4)
    const float* __restrict__ bf1,    // (16,)
    const float* __restrict__ Wf2,    // (1,16)
    const float* __restrict__ bf2,    // (1,)
    float* __restrict__ out)          // (4, B, T)
{
    __shared__ float a_sh[16][4];
    __shared__ float wf2_sh[16];
    __shared__ float bf1_sh[16];
    __shared__ float bf2_sh;

    if (threadIdx.x < 16) {
        const int f = threadIdx.x;
        float mx = fmaxf(fmaxf(lw[0], lw[1]), fmaxf(lw[2], lw[3]));
        float e0 = expf(lw[0] - mx), e1 = expf(lw[1] - mx);
        float e2 = expf(lw[2] - mx), e3 = expf(lw[3] - mx);
        float es = e0 + e1 + e2 + e3;
        float wl[4] = { e0 / es, e1 / es, e2 / es, e3 / es };
#pragma unroll
        for (int l = 0; l < 4; l++) {
            float s = 0.0f;
#pragma unroll
            for (int p = 0; p < 4; p++)
                s += 1.0f / (1.0f + expf(-imp[l * 4 + p]));
            float S  = s / (s + 1e-8f);
            a_sh[f][l] = Wf1[f * 4 + l] * (S * wl[l]);
        }
        wf2_sh[f] = Wf2[f];
        bf1_sh[f] = bf1[f];
        if (f == 0) bf2_sh = bf2[0];
    }
    __syncthreads();

    const int idx4 = (blockIdx.x * 256 + threadIdx.x) * 4;  // < BT exactly

#pragma unroll
    for (int p = 0; p < 4; p++) {
        float4 y[4];
#pragma unroll
        for (int l = 0; l < 4; l++)
            y[l] = *(const float4*)&g_outs[(l * 4 + p) * BT + idx4];

        float4 o = make_float4(bf2_sh, bf2_sh, bf2_sh, bf2_sh);
#pragma unroll
        for (int f = 0; f < 16; f++) {
            float4 h = make_float4(bf1_sh[f], bf1_sh[f], bf1_sh[f], bf1_sh[f]);
#pragma unroll
            for (int l = 0; l < 4; l++) {
                float a = a_sh[f][l];
                h.x = fmaf(a, y[l].x, h.x); h.y = fmaf(a, y[l].y, h.y);
                h.z = fmaf(a, y[l].z, h.z); h.w = fmaf(a, y[l].w, h.w);
            }
            float wf = wf2_sh[f];
            o.x = fmaf(wf, fmaxf(h.x, 0.0f), o.x);
            o.y = fmaf(wf, fmaxf(h.y, 0.0f), o.y);
            o.z = fmaf(wf, fmaxf(h.z, 0.0f), o.z);
            o.w = fmaf(wf, fmaxf(h.w, 0.0f), o.w);
        }
        *(float4*)&out[p * BT + idx4] = o;
    }
}

// ---------------------------------------------------------------------------
extern "C" void kernel_launch(void* const* d_in, const int* in_sizes, int n_in,
                              void* d_out, int out_size) {
    const float* x    = (const float*)d_in[0];
    const float* W1   = (const float*)d_in[1];
    const float* b1   = (const float*)d_in[2];
    const float* W2   = (const float*)d_in[3];
    const float* b2   = (const float*)d_in[4];
    const float* W3   = (const float*)d_in[5];
    const float* b3   = (const float*)d_in[6];
    const float* logE = (const float*)d_in[7];
    const float* loge = (const float*)d_in[8];
    const float* imp  = (const float*)d_in[9];
    const float* lw   = (const float*)d_in[10];
    const float* Wf1  = (const float*)d_in[11];
    const float* bf1  = (const float*)d_in[12];
    const float* Wf2  = (const float*)d_in[13];
    const float* bf2  = (const float*)d_in[14];
    float* out = (float*)d_out;

    pinn_scan_kernel<<<1024, 64>>>(x, W1, b1, W2, b2, W3, b3, logE, loge, imp);
    pinn_combine_kernel<<<BT / 1024, 256>>>(imp, lw, Wf1, bf1, Wf2, bf2, out);
}